// round 3
// baseline (speedup 1.0000x reference)
#include <cuda_runtime.h>
#include <cuda_bf16.h>
#include <math.h>

// Problem constants
#define BATCH 8
#define MDIM 256
#define NDIM 256
#define DDIM 512
#define NDIAG 511            // M + N - 1
#define INFV 100000000.0f    // matches reference _INF
#define GAMMA_MIN 0.0001f

// ---------------------------------------------------------------------------
// Scratch (static device globals; no allocation)
// layout: diag-major  [b][d][i]  with i = row index (global m), d = m + n
// ---------------------------------------------------------------------------
__device__ float g_rx[BATCH * MDIM];                 // 1/||x_m||
__device__ float g_ry[BATCH * NDIM];                 // 1/||y_n||
__device__ float g_cost[BATCH * NDIAG * MDIM];       // cost, diag-major
__device__ float g_R[BATCH * NDIAG * MDIM];          // R (interior), diag-major
__device__ float g_S[BATCH * NDIAG * MDIM];          // softmin value (= R - cost)

// ---------------------------------------------------------------------------
// Kernel 1: inverse row norms for x and y.  One warp per row.
// rows 0..2047 -> x, rows 2048..4095 -> y
// ---------------------------------------------------------------------------
__global__ __launch_bounds__(256) void norms_kernel(const float* __restrict__ x,
                                                    const float* __restrict__ y)
{
    int warp = threadIdx.x >> 5;
    int lane = threadIdx.x & 31;
    int row  = blockIdx.x * 8 + warp;          // 512 blocks * 8 warps = 4096 rows

    const float* base;
    float* out;
    if (row < BATCH * MDIM) {
        base = x + (size_t)row * DDIM;
        out  = g_rx + row;
    } else {
        int r = row - BATCH * MDIM;
        base = y + (size_t)r * DDIM;
        out  = g_ry + r;
    }

    const float4* b4 = reinterpret_cast<const float4*>(base);
    float s = 0.0f;
#pragma unroll
    for (int t = 0; t < 4; ++t) {
        float4 v = b4[lane + 32 * t];          // 128 float4 per row
        s += v.x * v.x + v.y * v.y + v.z * v.z + v.w * v.w;
    }
#pragma unroll
    for (int o = 16; o; o >>= 1) s += __shfl_xor_sync(0xFFFFFFFFu, s, o);

    if (lane == 0) {
        float n = sqrtf(s);
        n = fmaxf(n, 1e-8f);
        *out = 1.0f / n;
    }
}

// ---------------------------------------------------------------------------
// Kernel 2: cost = 1 - (x.y) * rx * ry, written DIAG-MAJOR.
// Tiled SGEMM: 64x64 tile per block, BK=16, 256 threads, 4x4 microtile.
// ---------------------------------------------------------------------------
#define BM 64
#define BN 64
#define BK 16

__global__ __launch_bounds__(256) void cost_kernel(const float* __restrict__ x,
                                                   const float* __restrict__ y)
{
    __shared__ float Xs[BK][BM + 1];
    __shared__ float Ys[BK][BN + 1];

    int b  = blockIdx.z;
    int m0 = blockIdx.y * BM;
    int n0 = blockIdx.x * BN;
    int tx = threadIdx.x;      // 0..15
    int ty = threadIdx.y;      // 0..15
    int tid = ty * 16 + tx;

    const float* xb = x + ((size_t)b * MDIM + m0) * DDIM;
    const float* yb = y + ((size_t)b * NDIM + n0) * DDIM;

    float acc[4][4];
#pragma unroll
    for (int r = 0; r < 4; ++r)
#pragma unroll
        for (int c = 0; c < 4; ++c) acc[r][c] = 0.0f;

    int kk = tid & 15;
    int rr = tid >> 4;

    for (int k0 = 0; k0 < DDIM; k0 += BK) {
#pragma unroll
        for (int r = 0; r < 4; ++r) {
            Xs[kk][rr + r * 16] = xb[(size_t)(rr + r * 16) * DDIM + k0 + kk];
            Ys[kk][rr + r * 16] = yb[(size_t)(rr + r * 16) * DDIM + k0 + kk];
        }
        __syncthreads();
#pragma unroll
        for (int k = 0; k < BK; ++k) {
            float a[4], bv[4];
#pragma unroll
            for (int r = 0; r < 4; ++r) a[r]  = Xs[k][ty * 4 + r];
#pragma unroll
            for (int c = 0; c < 4; ++c) bv[c] = Ys[k][tx * 4 + c];
#pragma unroll
            for (int r = 0; r < 4; ++r)
#pragma unroll
                for (int c = 0; c < 4; ++c) acc[r][c] += a[r] * bv[c];
        }
        __syncthreads();
    }

    float* costb = g_cost + (size_t)b * NDIAG * MDIM;
#pragma unroll
    for (int r = 0; r < 4; ++r) {
        int row = m0 + ty * 4 + r;
        float rx = g_rx[b * MDIM + row];
#pragma unroll
        for (int c = 0; c < 4; ++c) {
            int col = n0 + tx * 4 + c;
            float ry = g_ry[b * NDIM + col];
            float v = 1.0f - acc[r][c] * rx * ry;
            costb[(size_t)(row + col) * MDIM + row] = v;   // diag-major
        }
    }
}

// ---------------------------------------------------------------------------
// Kernel 3: forward soft-DTW wavefront.  One block per batch, thread = row i.
// Keeps the last two R diagonals in rotating shared buffers; writes R and the
// softmin value S diag-major to global for the backward pass.
// ---------------------------------------------------------------------------
__global__ __launch_bounds__(256) void fwd_kernel(const float* __restrict__ gamma_ptr,
                                                  float* __restrict__ d_out)
{
    __shared__ float buf[3][MDIM];

    int b = blockIdx.x;
    int i = threadIdx.x;

    float gv = fmaxf(fabsf(*gamma_ptr), GAMMA_MIN);
    float ig = 1.0f / gv;

    const float* costb = g_cost + (size_t)b * NDIAG * MDIM;
    float* Rb = g_R + (size_t)b * NDIAG * MDIM;
    float* Sb = g_S + (size_t)b * NDIAG * MDIM;

    int pa = 0, pb = 1, pc = 2;            // pa = diag d-2, pb = diag d-1, pc = new

    // prefetch cost for d = 0
    float cnext = costb[i];

    for (int d = 0; d < NDIAG; ++d) {
        int j = d - i;
        bool valid = (j >= 0) && (j < NDIM);

        float cv = cnext;
        if (d + 1 < NDIAG) cnext = costb[(size_t)(d + 1) * MDIM + i];

        // three-way softmin with explicit boundary semantics
        float a  = (i > 0 && j > 0) ? buf[pa][i - 1]
                                    : ((i == 0 && j == 0) ? 0.0f : INFV);
        float bb = (i > 0) ? buf[pb][i - 1] : INFV;
        float cc = (j > 0) ? buf[pb][i]     : INFV;

        float mn = fminf(a, fminf(bb, cc));
        float s  = __expf((mn - a)  * ig)
                 + __expf((mn - bb) * ig)
                 + __expf((mn - cc) * ig);
        float Sv = mn - gv * __logf(s);
        float Rv = cv + Sv;

        if (valid) {
            buf[pc][i] = Rv;
            Rb[(size_t)d * MDIM + i] = Rv;
            Sb[(size_t)d * MDIM + i] = Sv;
            if (d == NDIAG - 1) {
                // only i = 255 is valid on the last diagonal: the distance
                d_out[BATCH * MDIM * NDIM + b] = Rv;
            }
        }
        __syncthreads();
        int t = pa; pa = pb; pb = pc; pc = t;
    }
}

// ---------------------------------------------------------------------------
// Kernel 4: backward soft-DTW wavefront (alignment matrix E).
// Weights depend only on forward R/S -> prefetched 2 diagonals ahead and
// computed BEFORE the barrier; post-barrier path is LDS(E) + 3 FMA + STS.
// ---------------------------------------------------------------------------
__device__ __forceinline__ float clamp50(float v)
{
    return fminf(fmaxf(v, -50.0f), 50.0f);
}

__global__ __launch_bounds__(256) void bwd_kernel(const float* __restrict__ gamma_ptr,
                                                  float* __restrict__ d_out)
{
    __shared__ float E[3][MDIM];

    int b = blockIdx.x;
    int i = threadIdx.x;

    float gv = fmaxf(fabsf(*gamma_ptr), GAMMA_MIN);
    float ig = 1.0f / gv;

    const float* Rb = g_R + (size_t)b * NDIAG * MDIM;
    const float* Sb = g_S + (size_t)b * NDIAG * MDIM;
    float* outb = d_out + (size_t)b * MDIM * NDIM;

    // init: E[p2]=diag d+2 (all zero), E[p1]=diag d+1 (seeded), E[pcur]=scratch
    E[0][i] = 0.0f; E[1][i] = 0.0f; E[2][i] = 0.0f;
    if (i == MDIM - 1) {
        E[1][MDIM - 1] = 1.0f;                       // cell (255,255), diag 510
        outb[(MDIM - 1) * NDIM + (NDIM - 1)] = 1.0f; // alignment seed
    }
    __syncthreads();

    int p2 = 0, p1 = 1, pcur = 2;

    // -------- load group for diagonal d (global R/S only, no smem dep) -----
#define BWD_LOADS(dd, RC, S2, SN, SR)                                          \
    {                                                                          \
        int jj = (dd) - i;                                                     \
        bool v_  = (jj >= 0) && (jj < NDIM);                                   \
        bool vd_ = v_ && (i < MDIM - 1) && (jj < NDIM - 1);                    \
        bool vn_ = v_ && (i < MDIM - 1);                                       \
        bool vr_ = v_ && (jj < NDIM - 1);                                      \
        RC = v_  ? Rb[(size_t)(dd) * MDIM + i]           : 0.0f;               \
        S2 = vd_ ? Sb[(size_t)((dd) + 2) * MDIM + i + 1] : -INFV;              \
        SN = vn_ ? Sb[(size_t)((dd) + 1) * MDIM + i + 1] : -INFV;              \
        SR = vr_ ? Sb[(size_t)((dd) + 1) * MDIM + i]     : -INFV;              \
    }

    float rc0, S20, Sn0, Sr0;    // for diagonal d
    float rc1, S21, Sn1, Sr1;    // for diagonal d-1
    BWD_LOADS(NDIAG - 2, rc0, S20, Sn0, Sr0);   // d = 509
    BWD_LOADS(NDIAG - 3, rc1, S21, Sn1, Sr1);   // d = 508

    for (int d = NDIAG - 2; d >= 0; --d) {
        // weights (independent of the E recurrence)
        float wd = __expf(clamp50((S20 - rc0) * ig));
        float wn = __expf(clamp50((Sn0 - rc0) * ig));
        float wr = __expf(clamp50((Sr0 - rc0) * ig));

        // shift pipeline, prefetch d-2
        rc0 = rc1; S20 = S21; Sn0 = Sn1; Sr0 = Sr1;
        if (d >= 2) { BWD_LOADS(d - 2, rc1, S21, Sn1, Sr1); }

        int j = d - i;
        bool valid = (j >= 0) && (j < NDIM);
        bool vd = valid && (i < MDIM - 1) && (j < NDIM - 1);
        bool vn = valid && (i < MDIM - 1);
        bool vr = valid && (j < NDIM - 1);

        float e2 = vd ? E[p2][i + 1] : 0.0f;
        float en = vn ? E[p1][i + 1] : 0.0f;
        float er = vr ? E[p1][i]     : 0.0f;

        float Ev = e2 * wd + en * wn + er * wr;

        if (valid) {
            E[pcur][i] = Ev;
            outb[i * NDIM + j] = Ev;
        }
        __syncthreads();
        int t = p2; p2 = p1; p1 = pcur; pcur = t;
    }
#undef BWD_LOADS
}

// ---------------------------------------------------------------------------
// Launch.  Inputs (metadata order): x [8,256,512] f32, y [8,256,512] f32,
// gamma [] f32.  Output: alignment [8,256,256] then distance [8], f32.
// ---------------------------------------------------------------------------
extern "C" void kernel_launch(void* const* d_in, const int* in_sizes, int n_in,
                              void* d_out, int out_size)
{
    const float* x     = (const float*)d_in[0];
    const float* y     = (const float*)d_in[1];
    const float* gamma = (const float*)d_in[2];
    float* out = (float*)d_out;

    norms_kernel<<<512, 256>>>(x, y);
    cost_kernel<<<dim3(NDIM / BN, MDIM / BM, BATCH), dim3(16, 16)>>>(x, y);
    fwd_kernel<<<BATCH, 256>>>(gamma, out);
    bwd_kernel<<<BATCH, 256>>>(gamma, out);
}